// round 17
// baseline (speedup 1.0000x reference)
#include <cuda_runtime.h>
#include <cuda_bf16.h>
#include <math.h>

// Problem constants
#define NB 2
#define EE 16
#define CC 16
#define VV (64*128*128)              // 1,048,576 voxels per batch

#define CHUNK1 4096
#define P1_GX (VV / CHUNK1)          // 256 chunks per batch
#define P1_ITERS (CHUNK1 / 128)      // 32 float4-iterations per lane
#define P1_TOTAL (P1_GX * NB)        // 512 pass1 blocks (means ticket)

#define P2_THREADS 256
#define P2_G 4                       // float4-groups per thread
#define P2_GX (VV / (P2_THREADS * 4 * P2_G))   // 256 blocks per batch
#define P2_TOTAL (P2_GX * NB)        // 512 blocks (finalize ticket)

#define DELTA_VAR 0.5f
#define DELTA_DIST 1.5f

// Scratch (device globals; zero-initialized at load; finalize re-zeros them
// after consuming, so every call sees zeros -> deterministic).
__device__ float g_sums[NB][CC][EE];
__device__ float g_counts[NB][CC];
__device__ float g_means[NB][CC][EE];    // written by pass1's last block
__device__ float g_var[NB][CC];
__device__ unsigned int g_ticket1;
__device__ unsigned int g_ticket2;

// ---------------------------------------------------------------------------
// Pass 1: per-cluster sums + counts. float2-INTERLEAVED accumulators: warp w
// owns planes w (.x) and w+8 (.y) in ONE float2 array -> one LDS.64+STS.64
// RMW per element instead of two scalar pairs (half the smem instructions,
// half the RMW chain). Constant 2-way bank conflict (lanes l, l+16) = same
// crossbar cycles as the old conflict-free scalar pair. Depth-2 pipeline.
// smem: 32KB AB + 2KB C = 34KB; 512 blocks -> single wave co-resident.
// ---------------------------------------------------------------------------
__global__ __launch_bounds__(256)
void pass1_kernel(const float* __restrict__ x, const int* __restrict__ t) {
    __shared__ __align__(16) float accAB[8][CC * 64];  // 32 KB (float2 slots)
    __shared__ float accC[CC * 32];                    // 2 KB (counts, warp 0)
    __shared__ unsigned int s_t;

    const int n    = blockIdx.y;
    const int base = blockIdx.x * CHUNK1;
    const int tid  = threadIdx.x;
    const int w    = tid >> 5;
    const int lane = tid & 31;

    for (int i = tid; i < 8 * CC * 64; i += 256) (&accAB[0][0])[i] = 0.0f;
    for (int i = tid; i < CC * 32; i += 256) accC[i] = 0.0f;
    __syncthreads();

    float2* AB = (float2*)accAB[w];
    const float* xpA = x + ((size_t)n * EE + w    ) * VV + base;
    const float* xpB = x + ((size_t)n * EE + w + 8) * VV + base;
    const int*   tp  = t + (size_t)n * VV + base;

#define P1_RMW(LAB, VA, VB) do {                         \
        float2 cur = AB[(LAB) * 32 + lane];              \
        cur.x += (VA); cur.y += (VB);                    \
        AB[(LAB) * 32 + lane] = cur;                     \
    } while (0)

    // depth-2 pipeline: slots 0/1, 6 LDG.128 outstanding
    int i = lane * 4;
    float4 va0 = *(const float4*)(xpA + i);
    float4 vb0 = *(const float4*)(xpB + i);
    int4   lb0 = *(const int4*)(tp + i);
    float4 va1 = *(const float4*)(xpA + i + 128);
    float4 vb1 = *(const float4*)(xpB + i + 128);
    int4   lb1 = *(const int4*)(tp + i + 128);

    if (w == 0) {
        #pragma unroll 2
        for (int it = 0; it < P1_ITERS - 2; it++) {
            float4 va, vb; int4 lb;
            if (it & 1) {
                va = va1; vb = vb1; lb = lb1;
                va1 = *(const float4*)(xpA + i + 256);
                vb1 = *(const float4*)(xpB + i + 256);
                lb1 = *(const int4*)(tp + i + 256);
            } else {
                va = va0; vb = vb0; lb = lb0;
                va0 = *(const float4*)(xpA + i + 256);
                vb0 = *(const float4*)(xpB + i + 256);
                lb0 = *(const int4*)(tp + i + 256);
            }
            P1_RMW(lb.x, va.x, vb.x);  accC[lb.x * 32 + lane] += 1.0f;
            P1_RMW(lb.y, va.y, vb.y);  accC[lb.y * 32 + lane] += 1.0f;
            P1_RMW(lb.z, va.z, vb.z);  accC[lb.z * 32 + lane] += 1.0f;
            P1_RMW(lb.w, va.w, vb.w);  accC[lb.w * 32 + lane] += 1.0f;
            i += 128;
        }
        P1_RMW(lb0.x, va0.x, vb0.x);  accC[lb0.x * 32 + lane] += 1.0f;
        P1_RMW(lb0.y, va0.y, vb0.y);  accC[lb0.y * 32 + lane] += 1.0f;
        P1_RMW(lb0.z, va0.z, vb0.z);  accC[lb0.z * 32 + lane] += 1.0f;
        P1_RMW(lb0.w, va0.w, vb0.w);  accC[lb0.w * 32 + lane] += 1.0f;
        P1_RMW(lb1.x, va1.x, vb1.x);  accC[lb1.x * 32 + lane] += 1.0f;
        P1_RMW(lb1.y, va1.y, vb1.y);  accC[lb1.y * 32 + lane] += 1.0f;
        P1_RMW(lb1.z, va1.z, vb1.z);  accC[lb1.z * 32 + lane] += 1.0f;
        P1_RMW(lb1.w, va1.w, vb1.w);  accC[lb1.w * 32 + lane] += 1.0f;
    } else {
        #pragma unroll 2
        for (int it = 0; it < P1_ITERS - 2; it++) {
            float4 va, vb; int4 lb;
            if (it & 1) {
                va = va1; vb = vb1; lb = lb1;
                va1 = *(const float4*)(xpA + i + 256);
                vb1 = *(const float4*)(xpB + i + 256);
                lb1 = *(const int4*)(tp + i + 256);
            } else {
                va = va0; vb = vb0; lb = lb0;
                va0 = *(const float4*)(xpA + i + 256);
                vb0 = *(const float4*)(xpB + i + 256);
                lb0 = *(const int4*)(tp + i + 256);
            }
            P1_RMW(lb.x, va.x, vb.x);
            P1_RMW(lb.y, va.y, vb.y);
            P1_RMW(lb.z, va.z, vb.z);
            P1_RMW(lb.w, va.w, vb.w);
            i += 128;
        }
        P1_RMW(lb0.x, va0.x, vb0.x);
        P1_RMW(lb0.y, va0.y, vb0.y);
        P1_RMW(lb0.z, va0.z, vb0.z);
        P1_RMW(lb0.w, va0.w, vb0.w);
        P1_RMW(lb1.x, va1.x, vb1.x);
        P1_RMW(lb1.y, va1.y, vb1.y);
        P1_RMW(lb1.z, va1.z, vb1.z);
        P1_RMW(lb1.w, va1.w, vb1.w);
    }
#undef P1_RMW
    __syncwarp();

    #pragma unroll
    for (int c = 0; c < CC; c++) {
        float2 s2 = AB[c * 32 + lane];
        float sA = s2.x, sB = s2.y;
        #pragma unroll
        for (int o = 16; o > 0; o >>= 1) {
            sA += __shfl_xor_sync(0xffffffffu, sA, o);
            sB += __shfl_xor_sync(0xffffffffu, sB, o);
        }
        if (lane == 0) {
            atomicAdd(&g_sums[n][c][w],     sA);
            atomicAdd(&g_sums[n][c][w + 8], sB);
        }
        if (w == 0) {
            float sC = accC[c * 32 + lane];
            #pragma unroll
            for (int o = 16; o > 0; o >>= 1) sC += __shfl_xor_sync(0xffffffffu, sC, o);
            if (lane == 0) atomicAdd(&g_counts[n][c], sC);
        }
    }

    // ---- last pass1 block computes means once (no FDIV downstream) ----
    __threadfence();
    if (tid == 0) s_t = atomicAdd(&g_ticket1, 1u);
    __syncthreads();
    if (s_t != P1_TOTAL - 1) return;
    __threadfence();
    for (int i2 = tid; i2 < NB * CC * EE; i2 += 256) {
        int nn = i2 >> 8, c = (i2 >> 4) & 15, e = i2 & 15;
        g_means[nn][c][e] = g_sums[nn][c][e] / g_counts[nn][c];
    }
    if (tid == 0) g_ticket1 = 0u;
}

// ---------------------------------------------------------------------------
// Pass 2: variance term. Mean gather via LDS.128: each voxel reads its 16
// means as 4x float4 from a 16B-aligned stride-20 row (64 -> 16 LDS per
// warp-group, <=2-way phase conflicts). 256 threads x 4 groups, 512 blocks
// single-wave. Finalize FUSED into the last block via ticket.
// ---------------------------------------------------------------------------
__global__ __launch_bounds__(P2_THREADS)
void pass2_kernel(const float* __restrict__ x, const int* __restrict__ t,
                  float* __restrict__ out) {
    __shared__ __align__(16) float means_s[CC * 20];   // 16B-aligned rows
    __shared__ float vacc[8][CC * 32];      // 16 KB (8 warps)
    __shared__ float wpart[8][CC];
    __shared__ unsigned int s_ticket;

    const int n    = blockIdx.y;
    const int tid  = threadIdx.x;
    const int w    = tid >> 5;
    const int lane = tid & 31;

    if (tid < CC * EE) {
        int c = tid >> 4, e = tid & 15;
        means_s[c * 20 + e] = g_means[n][c][e];
    }
    for (int i = tid; i < 8 * CC * 32; i += P2_THREADS) (&vacc[0][0])[i] = 0.0f;
    __syncthreads();

    const float* xb = x + (size_t)n * EE * VV;
    const int*   tb = t + (size_t)n * VV;
    const int gbase = blockIdx.x * (P2_THREADS * P2_G);
    float* myv = vacc[w];

    int4 lb = *(const int4*)(tb + (size_t)(gbase + tid) * 4);

#define P2_VOX(SS, LAB, COMP) do {                                        \
        const float* mrow = means_s + (LAB) * 20 + eo;                    \
        float4 ma = *(const float4*)(mrow);                               \
        float4 mb = *(const float4*)(mrow + 4);                           \
        float d;                                                          \
        d = xv[0].COMP - ma.x; SS = fmaf(d, d, SS);                       \
        d = xv[1].COMP - ma.y; SS = fmaf(d, d, SS);                       \
        d = xv[2].COMP - ma.z; SS = fmaf(d, d, SS);                       \
        d = xv[3].COMP - ma.w; SS = fmaf(d, d, SS);                       \
        d = xv[4].COMP - mb.x; SS = fmaf(d, d, SS);                       \
        d = xv[5].COMP - mb.y; SS = fmaf(d, d, SS);                       \
        d = xv[6].COMP - mb.z; SS = fmaf(d, d, SS);                       \
        d = xv[7].COMP - mb.w; SS = fmaf(d, d, SS);                       \
    } while (0)

    #pragma unroll
    for (int g = 0; g < P2_G; g++) {
        const int v = (gbase + g * P2_THREADS + tid) * 4;
        int4 lbn;
        if (g + 1 < P2_G)
            lbn = *(const int4*)(tb + (size_t)(v + P2_THREADS * 4));

        float ss0 = 0.0f, ss1 = 0.0f, ss2 = 0.0f, ss3 = 0.0f;
        #pragma unroll
        for (int eo = 0; eo < EE; eo += 8) {
            float4 xv[8];
            #pragma unroll
            for (int e = 0; e < 8; e++)
                xv[e] = *(const float4*)(xb + (size_t)(eo + e) * VV + v);
            P2_VOX(ss0, lb.x, x);
            P2_VOX(ss1, lb.y, y);
            P2_VOX(ss2, lb.z, z);
            P2_VOX(ss3, lb.w, w);
        }

        float h;
        h = fmaxf(sqrtf(ss0) - DELTA_VAR, 0.0f); myv[lb.x * 32 + lane] += h * h;
        h = fmaxf(sqrtf(ss1) - DELTA_VAR, 0.0f); myv[lb.y * 32 + lane] += h * h;
        h = fmaxf(sqrtf(ss2) - DELTA_VAR, 0.0f); myv[lb.z * 32 + lane] += h * h;
        h = fmaxf(sqrtf(ss3) - DELTA_VAR, 0.0f); myv[lb.w * 32 + lane] += h * h;

        lb = lbn;
    }
#undef P2_VOX
    __syncwarp();

    #pragma unroll
    for (int c = 0; c < CC; c++) {
        float vv = myv[c * 32 + lane];
        #pragma unroll
        for (int o = 16; o > 0; o >>= 1) vv += __shfl_xor_sync(0xffffffffu, vv, o);
        if (lane == 0) wpart[w][c] = vv;
    }
    __syncthreads();

    if (tid < CC) {
        float s = 0.0f;
        #pragma unroll
        for (int ww = 0; ww < 8; ww++) s += wpart[ww][tid];
        atomicAdd(&g_var[n][tid], s);
    }

    // ---- fused finalize: globally last block does the tiny epilogue ----
    __threadfence();
    if (tid == 0) s_ticket = atomicAdd(&g_ticket2, 1u);
    __syncthreads();
    if (s_ticket != P2_TOTAL - 1) return;
    __threadfence();   // make all blocks' g_var visible

    __shared__ float accf[NB][3];           // [n][0]=var, [1]=dist, [2]=reg

    if (tid < NB * 3) (&accf[0][0])[tid] = 0.0f;
    __syncthreads();

    if (tid < NB * CC) {   // variance + regularizer terms
        int nn = tid >> 4, c = tid & 15;
        atomicAdd(&accf[nn][0], g_var[nn][c] / g_counts[nn][c]);
        float s = 0.0f;
        #pragma unroll
        for (int e = 0; e < EE; e++) {
            float m = g_means[nn][c][e];
            s = fmaf(m, m, s);
        }
        atomicAdd(&accf[nn][2], sqrtf(s));
    }

    for (int i = tid; i < NB * CC * CC; i += P2_THREADS) {  // all-pairs repulsion
        int nn = i >> 8, a = (i >> 4) & 15, b = i & 15;
        float s = 0.0f;
        #pragma unroll
        for (int e = 0; e < EE; e++) {
            float d = g_means[nn][a][e] - g_means[nn][b][e];
            s = fmaf(d, d, s);
        }
        float dmat = sqrtf(s);
        float rep  = (a == b) ? 0.0f : (2.0f * DELTA_DIST);
        float hh   = fmaxf(rep - dmat, 0.0f);
        atomicAdd(&accf[nn][1], hh * hh);
    }
    __syncthreads();

    if (tid == 0) {
        float loss = 0.0f;
        #pragma unroll
        for (int nn = 0; nn < NB; nn++) {
            float var_term  = accf[nn][0] / (float)CC;
            float dist_term = accf[nn][1] / (float)(CC * (CC - 1));
            float reg_term  = accf[nn][2] / (float)CC;
            loss += var_term + dist_term + 0.001f * reg_term;
        }
        out[0] = loss / (float)NB;
        g_ticket2 = 0u;
    }
    __syncthreads();

    // re-zero scratch for the next (graph-replay) invocation
    {
        float* s = &g_sums[0][0][0];
        for (int i = tid; i < NB * CC * EE; i += P2_THREADS) s[i] = 0.0f;
        float* c = &g_counts[0][0];
        for (int i = tid; i < NB * CC; i += P2_THREADS) c[i] = 0.0f;
        float* vv = &g_var[0][0];
        for (int i = tid; i < NB * CC; i += P2_THREADS) vv[i] = 0.0f;
    }
}

// ---------------------------------------------------------------------------
extern "C" void kernel_launch(void* const* d_in, const int* in_sizes, int n_in,
                              void* d_out, int out_size) {
    const float* x = (const float*)d_in[0];   // [2,16,64,128,128] f32
    const int*   t = (const int*)d_in[1];     // [2,64,128,128]    i32
    float* out = (float*)d_out;

    pass1_kernel<<<dim3(P1_GX, NB), 256>>>(x, t);
    pass2_kernel<<<dim3(P2_GX, NB), P2_THREADS>>>(x, t, out);
}